// round 15
// baseline (speedup 1.0000x reference)
#include <cuda_runtime.h>
#include <cstdint>

// ---------------- constants ----------------
#define T_FRAMES 2049
#define NWAV     262144
#define MW       16699
#define LEFT     24418
#define PADR     32768
#define NB       96
#define NC       20
#define EC2      1152           // [full 576 | partial 576] moment cols
#define GROWS    2368
#define XW_LEN   294912         // 2304*128
#define TPAD     2176

// stage-2 tiling: 18 complex freqs x 96 frames, 288 threads, 3 blocks/SM
#define FTILE2   18
#define TTILE2   96
#define TT2      22             // 22*96 = 2112 >= 2049
#define FB2      32
#define THR2     288
#define GS_STR   229            // float2 stride, rows 0..227
#define HS_STR   217            // rows 0..215
#define MP_STR   97             // rows 0..95
#define ZS_STR   97
#define W2ROWS   24

// setup kernel block ranges
#define PAD_BLKS 1152
#define E_BLKS   48             // 96 pairs x 128 r / 256
#define NF       576
#define W_ELEMS  (NF * W2ROWS)
#define W_BLKS   54
#define SETUP_BLKS (PAD_BLKS + E_BLKS + W_BLKS + 1)

// ---------------- device scratch ----------------
__device__ float g_xw[XW_LEN];
__device__ float g_e[128 * EC2];
__device__ float g_w2[W2ROWS * 1152];
__device__ float g_g[(size_t)GROWS * EC2];
__device__ float g_lpT[(size_t)NB * TPAD];      // log cqt power, [bin][t]
__device__ float g_c[NC * TPAD];                // cepstra, [c][t]
__device__ float g_alpha[NB];
__device__ float g_dct[NC * NB];

// ---------------- f32x2 helpers ----------------
__device__ __forceinline__ void fma2(unsigned long long& acc,
                                     unsigned long long a, unsigned long long b) {
    asm("fma.rn.f32x2 %0, %1, %2, %0;" : "+l"(acc) : "l"(a), "l"(b));
}
__device__ __forceinline__ unsigned long long dup2(float x) {
    unsigned long long r;
    asm("mov.b64 %0, {%1, %1};" : "=l"(r) : "f"(x));
    return r;
}
__device__ __forceinline__ unsigned long long pk2(float x, float y) {
    unsigned long long r;
    asm("mov.b64 %0, {%1, %2};" : "=l"(r) : "f"(x), "f"(y));
    return r;
}
__device__ __forceinline__ float2 upk2(unsigned long long v) {
    float2 r;
    asm("mov.b64 {%0, %1}, %2;" : "=f"(r.x), "=f"(r.y) : "l"(v));
    return r;
}

// ---------------- inline bin computation ----------------
__device__ __forceinline__ int bin_of(int bi) {   // bi 0..191
    int i = bi >> 1;
    float cq   = 32.7f * exp2f((float)i / 24.0f);
    float idxf = cq / 8000.0f * 32768.0f;
    int lo = (int)idxf;
    lo = max(0, min(lo, 32767));
    return lo + (bi & 1);
}

// rho offset for local freq index fi (0..17 within block)
__device__ __forceinline__ float rho_of(int fi) {
    int bl = fi / 3, j = fi - 3 * bl;
    int h = bl & 1;
    float sgn = (j == 1) ? -1.0f : (j == 2) ? 1.0f : 0.0f;
    return 6.283185307f * ((h ? 0.5f : -0.5f) * (1.0f / 65536.0f) + sgn * (1.0f / (float)MW));
}

// ---------------- fused setup ----------------
__global__ void __launch_bounds__(256) k_setup(const float* __restrict__ wav) {
    const int blk = blockIdx.x;
    const int tid = threadIdx.x;

    if (blk < PAD_BLKS) {
        int i = blk * 256 + tid;
        int q = i + (LEFT - PADR);
        int idx = (q < 0) ? -q : ((q >= NWAV) ? (2 * NWAV - 2 - q) : q);
        idx = max(0, min(idx, NWAV - 1));
        g_xw[i] = wav[idx];
        return;
    }
    if (blk < PAD_BLKS + E_BLKS) {
        // one sincospif per (pair, r); moments derived by r, r^2 scaling
        int lin = (blk - PAD_BLKS) * 256 + tid;     // 0..12287
        int p = lin % 96, r = lin / 96;
        int b = bin_of(2 * p);                      // lo bin of pair
        int mod = ((2 * b + 1) * r) & 131071;
        float x = (float)mod * (1.0f / 65536.0f);
        if (x >= 1.0f) x -= 2.0f;
        float s, c;
        sincospif(x, &s, &c);
        float re = c, im = -s;
        float rf = (float)r;
        float* e = g_e + r * EC2 + p * 6;
        e[0] = re;            e[1] = im;
        e[2] = rf * re;       e[3] = rf * im;
        e[4] = rf * rf * re;  e[5] = rf * rf * im;
        float zp = (r < 59) ? 1.0f : 0.0f;
        e[576]     = zp * re;            e[577]     = zp * im;
        e[578]     = zp * rf * re;       e[579]     = zp * rf * im;
        e[580]     = zp * rf * rf * re;  e[581]     = zp * rf * rf * im;
        return;
    }
    if (blk < PAD_BLKS + E_BLKS + W_BLKS) {
        int lin = (blk - PAD_BLKS - E_BLKS) * 256 + tid;
        if (lin >= W_ELEMS) return;
        int fi = lin / W2ROWS;
        int u  = lin % W2ROWS;
        int bi = fi / 3, j = fi % 3;
        int b  = bin_of(bi);
        int sgn = (j == 1) ? -1 : (j == 2) ? 1 : 0;
        float wre, wim;
        if (u < 13) {
            float fa = (float)((b * u) & 511) * (1.0f / 512.0f);
            float fbv = (float)(128 * u) * (1.0f / (float)MW);
            float fr = fa + (float)sgn * fbv;
            float s, c;
            sincospif(2.0f * fr, &s, &c);
            wre = c; wim = -s;
        } else {
            float coeff = (j == 0) ? 0.5f : -0.25f;
            int e = (u < 23) ? 13 * (u - 13) : 130;
            float fa = (float)((b * e) & 511) * (1.0f / 512.0f);
            float fbv = (float)((128 * e) % MW) * (1.0f / (float)MW);
            float fr = fa + (float)sgn * fbv;
            float s, c;
            sincospif(2.0f * fr, &s, &c);
            wre = coeff * c;
            wim = -coeff * s;
        }
        g_w2[u * 1152 + 2 * fi]     = wre;
        g_w2[u * 1152 + 2 * fi + 1] = wim;
        return;
    }
    // last block: alpha + dct
    if (tid < NB) {
        float cq   = 32.7f * exp2f((float)tid / 24.0f);
        float idxf = cq / 8000.0f * 32768.0f;
        int lo = (int)idxf;
        lo = max(0, min(lo, 32767));
        g_alpha[tid] = idxf - (float)lo;
    }
    for (int idx = tid; idx < NC * NB; idx += 256) {
        int c = idx / NB, n = idx % NB;
        g_dct[idx] = cospif((float)(c * (2 * n + 1)) / 192.0f);
    }
}

// ---------------- stage 1: moment GEMM, block 64 rows x 64 cols, 3 blocks/SM ----------------
__global__ void __launch_bounds__(256, 3) k_s1() {
    extern __shared__ float smem[];
    float* xs = smem;            // 8192 floats (32 KB)
    float* ts = smem + 8192;     // up to 128 x 64 (32 KB)

    const int bx = blockIdx.x;                 // 0..17
    const int c0 = (bx < 9) ? bx * 64 : 576 + (bx - 9) * 64;
    const int K  = (bx < 9) ? 128 : 64;
    const int s0 = blockIdx.y * 64;
    const int tid = threadIdx.x;
    const int cg = tid & 15;
    const int fg = tid >> 4;

    const float4* xsrc = (const float4*)(g_xw + s0 * 128);
    #pragma unroll
    for (int i = tid; i < 2048; i += 256)
        ((float4*)xs)[i] = xsrc[i];
    for (int i = tid; i < K * 16; i += 256) {
        int kk = i >> 4, c4 = i & 15;
        ((float4*)ts)[i] = *(const float4*)(g_e + kk * EC2 + c0 + c4 * 4);
    }
    __syncthreads();

    unsigned long long acc[4][2] = {};
    for (int kk0 = 0; kk0 < K; kk0 += 4) {
        float4 af[4];
        #pragma unroll
        for (int r = 0; r < 4; r++)
            af[r] = *(const float4*)(xs + (fg * 4 + r) * 128 + kk0);
        #pragma unroll
        for (int k = 0; k < 4; k++) {
            ulonglong2 bb = *(const ulonglong2*)(ts + (kk0 + k) * 64 + cg * 4);
            #pragma unroll
            for (int r = 0; r < 4; r++) {
                unsigned long long ad = dup2(((const float*)&af[r])[k]);
                fma2(acc[r][0], ad, bb.x);
                fma2(acc[r][1], ad, bb.y);
            }
        }
    }

    #pragma unroll
    for (int r = 0; r < 4; r++) {
        int s = s0 + fg * 4 + r;
        ulonglong2 v;
        v.x = acc[r][0]; v.y = acc[r][1];
        *(ulonglong2*)(g_g + (size_t)s * EC2 + c0 + cg * 4) = v;
    }
}

// ---------------- stage 2: moment expand + two-level FIR + fused power/log ----------------
__global__ void __launch_bounds__(THR2, 3) k_s2() {
    extern __shared__ float smem[];
    float2* Gs = (float2*)smem;               // [18][GS_STR], rows 0..227
    float2* Hs = Gs + FTILE2 * GS_STR;        // [18][HS_STR], rows 0..215; alias Ms[9][GS_STR]
    float2* Mp = Hs + FTILE2 * HS_STR;        // [9][MP_STR], rows 0..95
    float2* Wt = Mp + 9 * MP_STR;             // [24][18]

    const int m   = blockIdx.x;               // bin-triple 0..31
    const int t0  = blockIdx.y * TTILE2;
    const int tid = threadIdx.x;
    float2* Ms = Hs;                          // alias while loading

    for (int idx = tid; idx < 228 * 9; idx += THR2) {
        int row = idx / 9, q = idx % 9;
        Ms[q * GS_STR + row] = *(const float2*)(g_g + (size_t)(t0 + row) * EC2 + 18 * m + 2 * q);
    }
    for (int idx = tid; idx < 96 * 9; idx += THR2) {
        int row = idx / 9, q = idx % 9;
        Mp[q * MP_STR + row] = *(const float2*)(g_g + (size_t)(t0 + 130 + row) * EC2 + 576 + 18 * m + 2 * q);
    }
    for (int idx = tid; idx < W2ROWS * 9; idx += THR2) {
        int u = idx / 9, p = idx % 9;
        float4 v = *(const float4*)(g_w2 + u * 1152 + m * FTILE2 * 2 + p * 4);
        Wt[u * FTILE2 + 2 * p]     = make_float2(v.x, v.y);
        Wt[u * FTILE2 + 2 * p + 1] = make_float2(v.z, v.w);
    }
    __syncthreads();

    // ---- expand moments -> Gs (2nd-order Taylor), rows 0..227 ----
    for (int idx = tid; idx < 228 * 18; idx += THR2) {
        int fi = idx % 18, row = idx / 18;
        int pp = (fi / 3) >> 1;
        float rho = rho_of(fi);
        float r2 = 0.5f * rho * rho;
        float2 m0 = Ms[(pp * 3 + 0) * GS_STR + row];
        float2 m1 = Ms[(pp * 3 + 1) * GS_STR + row];
        float2 m2 = Ms[(pp * 3 + 2) * GS_STR + row];
        float2 g;
        g.x = m0.x + rho * m1.y - r2 * m2.x;
        g.y = m0.y - rho * m1.x - r2 * m2.y;
        Gs[fi * GS_STR + row] = g;
    }
    __syncthreads();

    // ---- H phase: H[tau,f] = sum_{w<13} rho^w G[tau+w,f], rows 0..215 ----
    for (int cid = tid; cid < 486; cid += THR2) {    // 18 f x 27 chunks of 8 rows
        int f = cid % 18, ch = cid / 18;
        int base = ch * 8;
        const float2* gb = Gs + f * GS_STR + base;
        unsigned long long gw[8], gsw[8], acc[8];
        #pragma unroll
        for (int r = 0; r < 8; r++) acc[r] = 0ULL;
        #pragma unroll
        for (int i = 0; i < 7; i++) {
            float2 g = gb[i];
            gw[i]  = pk2(g.x, g.y);
            gsw[i] = pk2(-g.y, g.x);
        }
        #pragma unroll
        for (int u = 0; u < 13; u++) {
            float2 g = gb[u + 7];
            gw[(u + 7) & 7]  = pk2(g.x, g.y);
            gsw[(u + 7) & 7] = pk2(-g.y, g.x);
            float2 wt = Wt[u * FTILE2 + f];
            unsigned long long wx = dup2(wt.x);
            unsigned long long wy = dup2(wt.y);
            #pragma unroll
            for (int r = 0; r < 8; r++) {
                fma2(acc[r], wx, gw[(u + r) & 7]);
                fma2(acc[r], wy, gsw[(u + r) & 7]);
            }
        }
        float2* hb = Hs + f * HS_STR + base;
        #pragma unroll
        for (int r = 0; r < 8; r++) hb[r] = upk2(acc[r]);
    }
    __syncthreads();

    // ---- Z phase: 10 coarse taps on H + 3 partial taps on Mp ----
    const int f  = tid % 18;
    const int tg = tid / 18;                   // 0..11 valid
    const bool active = (tid < 216);
    const int base = tg * 8;
    unsigned long long acc[8] = {};
    if (active) {
        const float2* hb = Hs + f * HS_STR + base;
        #pragma unroll
        for (int v = 0; v < 10; v++) {
            float2 wt = Wt[(13 + v) * FTILE2 + f];
            unsigned long long wx = dup2(wt.x);
            unsigned long long wy = dup2(wt.y);
            #pragma unroll
            for (int r = 0; r < 8; r++) {
                float2 h = hb[13 * v + r];
                fma2(acc[r], wx, pk2(h.x, h.y));
                fma2(acc[r], wy, pk2(-h.y, h.x));
            }
        }
        float2 wt = Wt[23 * FTILE2 + f];
        float rho = rho_of(f);
        float r2 = 0.5f * rho * rho;
        float2 W[3];
        W[0] = wt;
        W[1] = make_float2(rho * wt.y, -rho * wt.x);
        W[2] = make_float2(-r2 * wt.x, -r2 * wt.y);
        int pp = (f / 3) >> 1;
        #pragma unroll
        for (int mm = 0; mm < 3; mm++) {
            unsigned long long wx = dup2(W[mm].x);
            unsigned long long wy = dup2(W[mm].y);
            const float2* gp = Mp + (pp * 3 + mm) * MP_STR + base;
            #pragma unroll
            for (int r = 0; r < 8; r++) {
                float2 g = gp[r];
                fma2(acc[r], wx, pk2(g.x, g.y));
                fma2(acc[r], wy, pk2(-g.y, g.x));
            }
        }
    }
    __syncthreads();
    float2* Zs = Gs;
    if (active) {
        #pragma unroll
        for (int r = 0; r < 8; r++)
            Zs[f * ZS_STR + base + r] = upk2(acc[r]);
    }
    __syncthreads();

    // ---- combine triples -> power -> lerp -> log (288 tasks, 1 round) ----
    {
        int idx = tid;                         // 3*96 = 288 exactly
        int q  = idx / TTILE2;
        int tl = idx % TTILE2;
        int t  = t0 + tl;
        if (t < T_FRAMES) {
            const float2* zq = Zs + (6 * q) * ZS_STR + tl;
            float2 z0 = zq[0];
            float2 z1 = zq[ZS_STR];
            float2 z2 = zq[2 * ZS_STR];
            float2 z3 = zq[3 * ZS_STR];
            float2 z4 = zq[4 * ZS_STR];
            float2 z5 = zq[5 * ZS_STR];
            float lre = z0.x + z1.x + z2.x, lim = z0.y + z1.y + z2.y;
            float hre = z3.x + z4.x + z5.x, him = z3.y + z4.y + z5.y;
            float plo = lre * lre + lim * lim;
            float phi = hre * hre + him * him;
            int bin = 3 * m + q;
            float al = g_alpha[bin];
            float p = (1.0f - al) * plo + al * phi;
            g_lpT[(size_t)bin * TPAD + t] = logf(fmaxf(p, 1e-8f));
        }
    }
}

// ---------------- cep: DCT, thread = (frame, coeff), 4 accumulators ----------------
__global__ void __launch_bounds__(320) k_cep() {
    __shared__ float lps[NB * 16];            // [n][t], 6 KB
    __shared__ float dctt[NC * NB];           // [c][n], 7.5 KB
    const int tid = threadIdx.x;
    const int t0 = blockIdx.x * 16;

    for (int idx = tid; idx < NB * 4; idx += 320) {
        int n = idx >> 2, p = idx & 3;
        float4 v = *(const float4*)(g_lpT + (size_t)n * TPAD + t0 + p * 4);
        *(float4*)(lps + n * 16 + p * 4) = v;
    }
    for (int idx = tid; idx < NC * NB; idx += 320) dctt[idx] = g_dct[idx];
    __syncthreads();

    const int tl = tid & 15;
    const int c  = tid >> 4;                  // 0..19
    float a0 = 0.0f, a1 = 0.0f, a2 = 0.0f, a3 = 0.0f;
    #pragma unroll 4
    for (int n = 0; n < 24; n++) {
        a0 = fmaf(lps[n * 16 + tl],        dctt[c * NB + n],      a0);
        a1 = fmaf(lps[(n + 24) * 16 + tl], dctt[c * NB + n + 24], a1);
        a2 = fmaf(lps[(n + 48) * 16 + tl], dctt[c * NB + n + 48], a2);
        a3 = fmaf(lps[(n + 72) * 16 + tl], dctt[c * NB + n + 72], a3);
    }
    g_c[c * TPAD + t0 + tl] = (a0 + a1) + (a2 + a3);
}

// ---------------- fused normalize + delta + delta-delta ----------------
__global__ void __launch_bounds__(256) k_tail(float* __restrict__ out) {
    const int c = blockIdx.x;       // 0..19
    const int tid = threadIdx.x;
    __shared__ float cn[T_FRAMES];
    __shared__ float d1s[T_FRAMES];
    __shared__ float red[256];

    float s = 0.0f;
    for (int t = tid; t < T_FRAMES; t += 256) {
        float v = g_c[c * TPAD + t];
        cn[t] = v;
        s += v;
    }
    red[tid] = s; __syncthreads();
    for (int o = 128; o; o >>= 1) { if (tid < o) red[tid] += red[tid + o]; __syncthreads(); }
    float mean = red[0] / (float)T_FRAMES;
    __syncthreads();
    float ss = 0.0f;
    for (int t = tid; t < T_FRAMES; t += 256) { float d = cn[t] - mean; ss += d * d; }
    red[tid] = ss; __syncthreads();
    for (int o = 128; o; o >>= 1) { if (tid < o) red[tid] += red[tid + o]; __syncthreads(); }
    float inv = 1.0f / (sqrtf(red[0] / (float)(T_FRAMES - 1)) + 1e-8f);
    __syncthreads();
    for (int t = tid; t < T_FRAMES; t += 256) cn[t] = (cn[t] - mean) * inv;
    __syncthreads();

    for (int t = tid; t < T_FRAMES; t += 256) {
        int tp1 = min(t + 1, T_FRAMES - 1), tm1 = max(t - 1, 0);
        int tp2 = min(t + 2, T_FRAMES - 1), tm2 = max(t - 2, 0);
        float d = ((cn[tp1] - cn[tm1]) + 2.0f * (cn[tp2] - cn[tm2])) * 0.1f;
        d1s[t] = d;
        out[t * 60 + c]      = cn[t];
        out[t * 60 + 20 + c] = d;
    }
    __syncthreads();
    for (int t = tid; t < T_FRAMES; t += 256) {
        int tp1 = min(t + 1, T_FRAMES - 1), tm1 = max(t - 1, 0);
        int tp2 = min(t + 2, T_FRAMES - 1), tm2 = max(t - 2, 0);
        float d = ((d1s[tp1] - d1s[tm1]) + 2.0f * (d1s[tp2] - d1s[tm2])) * 0.1f;
        out[t * 60 + 40 + c] = d;
    }
}

// ---------------- launch ----------------
extern "C" void kernel_launch(void* const* d_in, const int* in_sizes, int n_in,
                              void* d_out, int out_size) {
    const float* wav = (const float*)d_in[0];
    float* out = (float*)d_out;

    const int s1_smem = (8192 + 128 * 64) * 4;    // 65536
    const int s2_smem = (FTILE2 * GS_STR + FTILE2 * HS_STR + 9 * MP_STR
                         + W2ROWS * FTILE2) * 8;  // 74664
    cudaFuncSetAttribute(k_s1, cudaFuncAttributeMaxDynamicSharedMemorySize, s1_smem);
    cudaFuncSetAttribute(k_s2, cudaFuncAttributeMaxDynamicSharedMemorySize, s2_smem);

    k_setup<<<SETUP_BLKS, 256>>>(wav);
    k_s1<<<dim3(18, 36), 256, s1_smem>>>();
    k_s2<<<dim3(FB2, TT2), THR2, s2_smem>>>();
    k_cep<<<TPAD / 16, 320>>>();
    k_tail<<<NC, 256>>>(out);
}

// round 16
// speedup vs baseline: 1.0005x; 1.0005x over previous
#include <cuda_runtime.h>
#include <cstdint>

// ---------------- constants ----------------
#define T_FRAMES 2049
#define NWAV     262144
#define MW       16699
#define LEFT     24418
#define PADR     32768
#define NB       96
#define NC       20
#define EC2      1152           // [full 576 | partial 576] moment cols
#define GROWS    2368
#define XW_LEN   294912         // 2304*128
#define TPAD     2176

// stage-2 tiling: 18 complex freqs x 96 frames, 288 threads, 3 blocks/SM
#define FTILE2   18
#define TTILE2   96
#define TT2      22             // 22*96 = 2112 >= 2049
#define FB2      32
#define THR2     288
#define GS_STR   229            // float2 stride, rows 0..227
#define HS_STR   217            // rows 0..215
#define MP_STR   97             // rows 0..95
#define ZS_STR   97
#define W2ROWS   24

// setup kernel block ranges
#define PAD_BLKS 1152
#define E_BLKS   48             // 96 pairs x 128 r / 256
#define NF       576
#define W_ELEMS  (NF * W2ROWS)
#define W_BLKS   54
#define SETUP_BLKS (PAD_BLKS + E_BLKS + W_BLKS + 1)

// ---------------- device scratch ----------------
__device__ float g_xw[XW_LEN];
__device__ float g_e[128 * EC2];
__device__ float g_w2[W2ROWS * 1152];
__device__ float g_g[(size_t)GROWS * EC2];
__device__ float g_lpT[(size_t)NB * TPAD];      // log cqt power, [bin][t]
__device__ float g_c[NC * TPAD];                // cepstra, [c][t]
__device__ float g_alpha[NB];
__device__ float g_dct[NC * NB];

// ---------------- f32x2 helpers ----------------
__device__ __forceinline__ void fma2(unsigned long long& acc,
                                     unsigned long long a, unsigned long long b) {
    asm("fma.rn.f32x2 %0, %1, %2, %0;" : "+l"(acc) : "l"(a), "l"(b));
}
__device__ __forceinline__ unsigned long long dup2(float x) {
    unsigned long long r;
    asm("mov.b64 %0, {%1, %1};" : "=l"(r) : "f"(x));
    return r;
}
__device__ __forceinline__ unsigned long long pk2(float x, float y) {
    unsigned long long r;
    asm("mov.b64 %0, {%1, %2};" : "=l"(r) : "f"(x), "f"(y));
    return r;
}
__device__ __forceinline__ float2 upk2(unsigned long long v) {
    float2 r;
    asm("mov.b64 {%0, %1}, %2;" : "=f"(r.x), "=f"(r.y) : "l"(v));
    return r;
}

// ---------------- inline bin computation ----------------
__device__ __forceinline__ int bin_of(int bi) {   // bi 0..191
    int i = bi >> 1;
    float cq   = 32.7f * exp2f((float)i / 24.0f);
    float idxf = cq / 8000.0f * 32768.0f;
    int lo = (int)idxf;
    lo = max(0, min(lo, 32767));
    return lo + (bi & 1);
}

// rho offset for local freq index fi (0..17 within block)
__device__ __forceinline__ float rho_of(int fi) {
    int bl = fi / 3, j = fi - 3 * bl;
    int h = bl & 1;
    float sgn = (j == 1) ? -1.0f : (j == 2) ? 1.0f : 0.0f;
    return 6.283185307f * ((h ? 0.5f : -0.5f) * (1.0f / 65536.0f) + sgn * (1.0f / (float)MW));
}

// ---------------- fused setup ----------------
__global__ void __launch_bounds__(256) k_setup(const float* __restrict__ wav) {
    const int blk = blockIdx.x;
    const int tid = threadIdx.x;

    if (blk < PAD_BLKS) {
        int i = blk * 256 + tid;
        int q = i + (LEFT - PADR);
        int idx = (q < 0) ? -q : ((q >= NWAV) ? (2 * NWAV - 2 - q) : q);
        idx = max(0, min(idx, NWAV - 1));
        g_xw[i] = wav[idx];
        return;
    }
    if (blk < PAD_BLKS + E_BLKS) {
        // one sincospif per (pair, r); moments derived by r, r^2 scaling
        int lin = (blk - PAD_BLKS) * 256 + tid;     // 0..12287
        int p = lin % 96, r = lin / 96;
        int b = bin_of(2 * p);                      // lo bin of pair
        int mod = ((2 * b + 1) * r) & 131071;
        float x = (float)mod * (1.0f / 65536.0f);
        if (x >= 1.0f) x -= 2.0f;
        float s, c;
        sincospif(x, &s, &c);
        float re = c, im = -s;
        float rf = (float)r;
        float* e = g_e + r * EC2 + p * 6;
        e[0] = re;            e[1] = im;
        e[2] = rf * re;       e[3] = rf * im;
        e[4] = rf * rf * re;  e[5] = rf * rf * im;
        float zp = (r < 59) ? 1.0f : 0.0f;
        e[576]     = zp * re;            e[577]     = zp * im;
        e[578]     = zp * rf * re;       e[579]     = zp * rf * im;
        e[580]     = zp * rf * rf * re;  e[581]     = zp * rf * rf * im;
        return;
    }
    if (blk < PAD_BLKS + E_BLKS + W_BLKS) {
        int lin = (blk - PAD_BLKS - E_BLKS) * 256 + tid;
        if (lin >= W_ELEMS) return;
        int fi = lin / W2ROWS;
        int u  = lin % W2ROWS;
        int bi = fi / 3, j = fi % 3;
        int b  = bin_of(bi);
        int sgn = (j == 1) ? -1 : (j == 2) ? 1 : 0;
        float wre, wim;
        if (u < 13) {
            float fa = (float)((b * u) & 511) * (1.0f / 512.0f);
            float fbv = (float)(128 * u) * (1.0f / (float)MW);
            float fr = fa + (float)sgn * fbv;
            float s, c;
            sincospif(2.0f * fr, &s, &c);
            wre = c; wim = -s;
        } else {
            float coeff = (j == 0) ? 0.5f : -0.25f;
            int e = (u < 23) ? 13 * (u - 13) : 130;
            float fa = (float)((b * e) & 511) * (1.0f / 512.0f);
            float fbv = (float)((128 * e) % MW) * (1.0f / (float)MW);
            float fr = fa + (float)sgn * fbv;
            float s, c;
            sincospif(2.0f * fr, &s, &c);
            wre = coeff * c;
            wim = -coeff * s;
        }
        g_w2[u * 1152 + 2 * fi]     = wre;
        g_w2[u * 1152 + 2 * fi + 1] = wim;
        return;
    }
    // last block: alpha + dct
    if (tid < NB) {
        float cq   = 32.7f * exp2f((float)tid / 24.0f);
        float idxf = cq / 8000.0f * 32768.0f;
        int lo = (int)idxf;
        lo = max(0, min(lo, 32767));
        g_alpha[tid] = idxf - (float)lo;
    }
    for (int idx = tid; idx < NC * NB; idx += 256) {
        int c = idx / NB, n = idx % NB;
        g_dct[idx] = cospif((float)(c * (2 * n + 1)) / 192.0f);
    }
}

// ---------------- stage 1: moment GEMM, block 64 rows x 64 cols, 3 blocks/SM ----------------
__global__ void __launch_bounds__(256, 3) k_s1() {
    extern __shared__ float smem[];
    float* xs = smem;            // 8192 floats (32 KB)
    float* ts = smem + 8192;     // up to 128 x 64 (32 KB)

    const int bx = blockIdx.x;                 // 0..17
    const int c0 = (bx < 9) ? bx * 64 : 576 + (bx - 9) * 64;
    const int K  = (bx < 9) ? 128 : 64;
    const int s0 = blockIdx.y * 64;
    const int tid = threadIdx.x;
    const int cg = tid & 15;
    const int fg = tid >> 4;

    const float4* xsrc = (const float4*)(g_xw + s0 * 128);
    #pragma unroll
    for (int i = tid; i < 2048; i += 256)
        ((float4*)xs)[i] = xsrc[i];
    for (int i = tid; i < K * 16; i += 256) {
        int kk = i >> 4, c4 = i & 15;
        ((float4*)ts)[i] = *(const float4*)(g_e + kk * EC2 + c0 + c4 * 4);
    }
    __syncthreads();

    unsigned long long acc[4][2] = {};
    for (int kk0 = 0; kk0 < K; kk0 += 4) {
        float4 af[4];
        #pragma unroll
        for (int r = 0; r < 4; r++)
            af[r] = *(const float4*)(xs + (fg * 4 + r) * 128 + kk0);
        #pragma unroll
        for (int k = 0; k < 4; k++) {
            ulonglong2 bb = *(const ulonglong2*)(ts + (kk0 + k) * 64 + cg * 4);
            #pragma unroll
            for (int r = 0; r < 4; r++) {
                unsigned long long ad = dup2(((const float*)&af[r])[k]);
                fma2(acc[r][0], ad, bb.x);
                fma2(acc[r][1], ad, bb.y);
            }
        }
    }

    #pragma unroll
    for (int r = 0; r < 4; r++) {
        int s = s0 + fg * 4 + r;
        ulonglong2 v;
        v.x = acc[r][0]; v.y = acc[r][1];
        *(ulonglong2*)(g_g + (size_t)s * EC2 + c0 + cg * 4) = v;
    }
}

// ---------------- stage 2: moment expand + two-level FIR + fused power/log ----------------
__global__ void __launch_bounds__(THR2, 3) k_s2() {
    extern __shared__ float smem[];
    float2* Gs = (float2*)smem;               // [18][GS_STR], rows 0..227
    float2* Hs = Gs + FTILE2 * GS_STR;        // [18][HS_STR], rows 0..215; alias Ms[9][GS_STR]
    float2* Mp = Hs + FTILE2 * HS_STR;        // [9][MP_STR], rows 0..95
    float2* Wt = Mp + 9 * MP_STR;             // [24][18]

    const int m   = blockIdx.x;               // bin-triple 0..31
    const int t0  = blockIdx.y * TTILE2;
    const int tid = threadIdx.x;
    float2* Ms = Hs;                          // alias while loading

    for (int idx = tid; idx < 228 * 9; idx += THR2) {
        int row = idx / 9, q = idx % 9;
        Ms[q * GS_STR + row] = *(const float2*)(g_g + (size_t)(t0 + row) * EC2 + 18 * m + 2 * q);
    }
    for (int idx = tid; idx < 96 * 9; idx += THR2) {
        int row = idx / 9, q = idx % 9;
        Mp[q * MP_STR + row] = *(const float2*)(g_g + (size_t)(t0 + 130 + row) * EC2 + 576 + 18 * m + 2 * q);
    }
    for (int idx = tid; idx < W2ROWS * 9; idx += THR2) {
        int u = idx / 9, p = idx % 9;
        float4 v = *(const float4*)(g_w2 + u * 1152 + m * FTILE2 * 2 + p * 4);
        Wt[u * FTILE2 + 2 * p]     = make_float2(v.x, v.y);
        Wt[u * FTILE2 + 2 * p + 1] = make_float2(v.z, v.w);
    }
    __syncthreads();

    // ---- expand moments -> Gs (2nd-order Taylor), rows 0..227 ----
    for (int idx = tid; idx < 228 * 18; idx += THR2) {
        int fi = idx % 18, row = idx / 18;
        int pp = (fi / 3) >> 1;
        float rho = rho_of(fi);
        float r2 = 0.5f * rho * rho;
        float2 m0 = Ms[(pp * 3 + 0) * GS_STR + row];
        float2 m1 = Ms[(pp * 3 + 1) * GS_STR + row];
        float2 m2 = Ms[(pp * 3 + 2) * GS_STR + row];
        float2 g;
        g.x = m0.x + rho * m1.y - r2 * m2.x;
        g.y = m0.y - rho * m1.x - r2 * m2.y;
        Gs[fi * GS_STR + row] = g;
    }
    __syncthreads();

    // ---- H phase: H[tau,f] = sum_{w<13} rho^w G[tau+w,f], rows 0..215 ----
    for (int cid = tid; cid < 486; cid += THR2) {    // 18 f x 27 chunks of 8 rows
        int f = cid % 18, ch = cid / 18;
        int base = ch * 8;
        const float2* gb = Gs + f * GS_STR + base;
        unsigned long long gw[8], gsw[8], acc[8];
        #pragma unroll
        for (int r = 0; r < 8; r++) acc[r] = 0ULL;
        #pragma unroll
        for (int i = 0; i < 7; i++) {
            float2 g = gb[i];
            gw[i]  = pk2(g.x, g.y);
            gsw[i] = pk2(-g.y, g.x);
        }
        #pragma unroll
        for (int u = 0; u < 13; u++) {
            float2 g = gb[u + 7];
            gw[(u + 7) & 7]  = pk2(g.x, g.y);
            gsw[(u + 7) & 7] = pk2(-g.y, g.x);
            float2 wt = Wt[u * FTILE2 + f];
            unsigned long long wx = dup2(wt.x);
            unsigned long long wy = dup2(wt.y);
            #pragma unroll
            for (int r = 0; r < 8; r++) {
                fma2(acc[r], wx, gw[(u + r) & 7]);
                fma2(acc[r], wy, gsw[(u + r) & 7]);
            }
        }
        float2* hb = Hs + f * HS_STR + base;
        #pragma unroll
        for (int r = 0; r < 8; r++) hb[r] = upk2(acc[r]);
    }
    __syncthreads();

    // ---- Z phase: 10 coarse taps on H + 3 partial taps on Mp ----
    const int f  = tid % 18;
    const int tg = tid / 18;                   // 0..11 valid
    const bool active = (tid < 216);
    const int base = tg * 8;
    unsigned long long acc[8] = {};
    if (active) {
        const float2* hb = Hs + f * HS_STR + base;
        #pragma unroll
        for (int v = 0; v < 10; v++) {
            float2 wt = Wt[(13 + v) * FTILE2 + f];
            unsigned long long wx = dup2(wt.x);
            unsigned long long wy = dup2(wt.y);
            #pragma unroll
            for (int r = 0; r < 8; r++) {
                float2 h = hb[13 * v + r];
                fma2(acc[r], wx, pk2(h.x, h.y));
                fma2(acc[r], wy, pk2(-h.y, h.x));
            }
        }
        float2 wt = Wt[23 * FTILE2 + f];
        float rho = rho_of(f);
        float r2 = 0.5f * rho * rho;
        float2 W[3];
        W[0] = wt;
        W[1] = make_float2(rho * wt.y, -rho * wt.x);
        W[2] = make_float2(-r2 * wt.x, -r2 * wt.y);
        int pp = (f / 3) >> 1;
        #pragma unroll
        for (int mm = 0; mm < 3; mm++) {
            unsigned long long wx = dup2(W[mm].x);
            unsigned long long wy = dup2(W[mm].y);
            const float2* gp = Mp + (pp * 3 + mm) * MP_STR + base;
            #pragma unroll
            for (int r = 0; r < 8; r++) {
                float2 g = gp[r];
                fma2(acc[r], wx, pk2(g.x, g.y));
                fma2(acc[r], wy, pk2(-g.y, g.x));
            }
        }
    }
    __syncthreads();
    float2* Zs = Gs;
    if (active) {
        #pragma unroll
        for (int r = 0; r < 8; r++)
            Zs[f * ZS_STR + base + r] = upk2(acc[r]);
    }
    __syncthreads();

    // ---- combine triples -> power -> lerp -> log (288 tasks, 1 round) ----
    {
        int idx = tid;                         // 3*96 = 288 exactly
        int q  = idx / TTILE2;
        int tl = idx % TTILE2;
        int t  = t0 + tl;
        if (t < T_FRAMES) {
            const float2* zq = Zs + (6 * q) * ZS_STR + tl;
            float2 z0 = zq[0];
            float2 z1 = zq[ZS_STR];
            float2 z2 = zq[2 * ZS_STR];
            float2 z3 = zq[3 * ZS_STR];
            float2 z4 = zq[4 * ZS_STR];
            float2 z5 = zq[5 * ZS_STR];
            float lre = z0.x + z1.x + z2.x, lim = z0.y + z1.y + z2.y;
            float hre = z3.x + z4.x + z5.x, him = z3.y + z4.y + z5.y;
            float plo = lre * lre + lim * lim;
            float phi = hre * hre + him * him;
            int bin = 3 * m + q;
            float al = g_alpha[bin];
            float p = (1.0f - al) * plo + al * phi;
            g_lpT[(size_t)bin * TPAD + t] = logf(fmaxf(p, 1e-8f));
        }
    }
}

// ---------------- cep: DCT, thread = (frame, coeff), 4 accumulators ----------------
__global__ void __launch_bounds__(320) k_cep() {
    __shared__ float lps[NB * 16];            // [n][t], 6 KB
    __shared__ float dctt[NC * NB];           // [c][n], 7.5 KB
    const int tid = threadIdx.x;
    const int t0 = blockIdx.x * 16;

    for (int idx = tid; idx < NB * 4; idx += 320) {
        int n = idx >> 2, p = idx & 3;
        float4 v = *(const float4*)(g_lpT + (size_t)n * TPAD + t0 + p * 4);
        *(float4*)(lps + n * 16 + p * 4) = v;
    }
    for (int idx = tid; idx < NC * NB; idx += 320) dctt[idx] = g_dct[idx];
    __syncthreads();

    const int tl = tid & 15;
    const int c  = tid >> 4;                  // 0..19
    float a0 = 0.0f, a1 = 0.0f, a2 = 0.0f, a3 = 0.0f;
    #pragma unroll 4
    for (int n = 0; n < 24; n++) {
        a0 = fmaf(lps[n * 16 + tl],        dctt[c * NB + n],      a0);
        a1 = fmaf(lps[(n + 24) * 16 + tl], dctt[c * NB + n + 24], a1);
        a2 = fmaf(lps[(n + 48) * 16 + tl], dctt[c * NB + n + 48], a2);
        a3 = fmaf(lps[(n + 72) * 16 + tl], dctt[c * NB + n + 72], a3);
    }
    g_c[c * TPAD + t0 + tl] = (a0 + a1) + (a2 + a3);
}

// ---------------- fused normalize + delta + delta-delta ----------------
__global__ void __launch_bounds__(256) k_tail(float* __restrict__ out) {
    const int c = blockIdx.x;       // 0..19
    const int tid = threadIdx.x;
    __shared__ float cn[T_FRAMES];
    __shared__ float d1s[T_FRAMES];
    __shared__ float red[256];

    float s = 0.0f;
    for (int t = tid; t < T_FRAMES; t += 256) {
        float v = g_c[c * TPAD + t];
        cn[t] = v;
        s += v;
    }
    red[tid] = s; __syncthreads();
    for (int o = 128; o; o >>= 1) { if (tid < o) red[tid] += red[tid + o]; __syncthreads(); }
    float mean = red[0] / (float)T_FRAMES;
    __syncthreads();
    float ss = 0.0f;
    for (int t = tid; t < T_FRAMES; t += 256) { float d = cn[t] - mean; ss += d * d; }
    red[tid] = ss; __syncthreads();
    for (int o = 128; o; o >>= 1) { if (tid < o) red[tid] += red[tid + o]; __syncthreads(); }
    float inv = 1.0f / (sqrtf(red[0] / (float)(T_FRAMES - 1)) + 1e-8f);
    __syncthreads();
    for (int t = tid; t < T_FRAMES; t += 256) cn[t] = (cn[t] - mean) * inv;
    __syncthreads();

    for (int t = tid; t < T_FRAMES; t += 256) {
        int tp1 = min(t + 1, T_FRAMES - 1), tm1 = max(t - 1, 0);
        int tp2 = min(t + 2, T_FRAMES - 1), tm2 = max(t - 2, 0);
        float d = ((cn[tp1] - cn[tm1]) + 2.0f * (cn[tp2] - cn[tm2])) * 0.1f;
        d1s[t] = d;
        out[t * 60 + c]      = cn[t];
        out[t * 60 + 20 + c] = d;
    }
    __syncthreads();
    for (int t = tid; t < T_FRAMES; t += 256) {
        int tp1 = min(t + 1, T_FRAMES - 1), tm1 = max(t - 1, 0);
        int tp2 = min(t + 2, T_FRAMES - 1), tm2 = max(t - 2, 0);
        float d = ((d1s[tp1] - d1s[tm1]) + 2.0f * (d1s[tp2] - d1s[tm2])) * 0.1f;
        out[t * 60 + 40 + c] = d;
    }
}

// ---------------- launch ----------------
extern "C" void kernel_launch(void* const* d_in, const int* in_sizes, int n_in,
                              void* d_out, int out_size) {
    const float* wav = (const float*)d_in[0];
    float* out = (float*)d_out;

    const int s1_smem = (8192 + 128 * 64) * 4;    // 65536
    const int s2_smem = (FTILE2 * GS_STR + FTILE2 * HS_STR + 9 * MP_STR
                         + W2ROWS * FTILE2) * 8;  // 74664
    cudaFuncSetAttribute(k_s1, cudaFuncAttributeMaxDynamicSharedMemorySize, s1_smem);
    cudaFuncSetAttribute(k_s2, cudaFuncAttributeMaxDynamicSharedMemorySize, s2_smem);

    k_setup<<<SETUP_BLKS, 256>>>(wav);
    k_s1<<<dim3(18, 36), 256, s1_smem>>>();
    k_s2<<<dim3(FB2, TT2), THR2, s2_smem>>>();
    k_cep<<<TPAD / 16, 320>>>();
    k_tail<<<NC, 256>>>(out);
}